// round 2
// baseline (speedup 1.0000x reference)
#include <cuda_runtime.h>
#include <cstdint>
#include <cstddef>

#define CHANNELS 1024
#define PIVOT 16384

// ---------------- PTX helpers ----------------
__device__ __forceinline__ uint32_t smem_addr(const void* p) {
    uint32_t r;
    asm("{ .reg .u64 t; cvta.to.shared.u64 t, %1; cvt.u32.u64 %0, t; }" : "=r"(r) : "l"(p));
    return r;
}
__device__ __forceinline__ void cp_async16(uint32_t d, const void* s) {
    asm volatile("cp.async.cg.shared.global [%0], [%1], 16;" :: "r"(d), "l"(s));
}
__device__ __forceinline__ void cp_commit() { asm volatile("cp.async.commit_group;"); }
template<int N> __device__ __forceinline__ void cp_wait() {
    asm volatile("cp.async.wait_group %0;" :: "n"(N));
}
__device__ __forceinline__ uint32_t f2tf32(float x) {
    uint32_t r; asm("cvt.rna.tf32.f32 %0, %1;" : "=r"(r) : "f"(x)); return r;
}
__device__ __forceinline__ void mma_tf32(float d[4], const uint32_t a[4], const uint32_t b[2]) {
    asm volatile(
        "mma.sync.aligned.m16n8k8.row.col.f32.tf32.tf32.f32 "
        "{%0,%1,%2,%3}, {%4,%5,%6,%7}, {%8,%9}, {%0,%1,%2,%3};"
        : "+f"(d[0]), "+f"(d[1]), "+f"(d[2]), "+f"(d[3])
        : "r"(a[0]), "r"(a[1]), "r"(a[2]), "r"(a[3]), "r"(b[0]), "r"(b[1]));
}

// Shared memory: per stage, A tile 4608 floats + B tile 4608 floats.
// K1: As[128][36] (pad 36 -> conflict-free fragment LDS)
// K2: As[64][72]  (p-major, interleaved k pairs; conflict-free)
// B (W tile) always Bs[128][36].
#define STAGE_FLOATS 9216
#define SMEM_BYTES (2 * STAGE_FLOATS * 4)

// ============================================================
// Kernel 1: out[0:PIVOT] = tanh(X @ W^T + b)
// block tile 128x128, k-tile 32, 8 warps (4x2), warp tile 32x64
// ============================================================
__global__ void __launch_bounds__(256) k1_gemm_tanh(
    const float* __restrict__ X, const float* __restrict__ W,
    const float* __restrict__ bias, float* __restrict__ out)
{
    extern __shared__ float smem[];
    const int tid  = threadIdx.x;
    const int lane = tid & 31, warp = tid >> 5;
    const int gid  = lane >> 2, tig = lane & 3;
    const int wm   = warp >> 1, wn  = warp & 1;
    const int m0   = blockIdx.y * 128, n0 = blockIdx.x * 128;
    const int lrow = tid >> 3, lcol = (tid & 7) * 4;

    float acc[2][8][4];
    #pragma unroll
    for (int i = 0; i < 2; i++)
        #pragma unroll
        for (int j = 0; j < 8; j++)
            #pragma unroll
            for (int k = 0; k < 4; k++) acc[i][j][k] = 0.f;

    auto issue = [&](int kt, int st) {
        float* As = smem + st * STAGE_FLOATS;
        float* Bs = As + 4608;
        const int k0 = kt * 32;
        #pragma unroll
        for (int it = 0; it < 4; it++) {
            int r = lrow + it * 32;
            cp_async16(smem_addr(&As[r * 36 + lcol]),
                       X + (size_t)(m0 + r) * CHANNELS + k0 + lcol);
            cp_async16(smem_addr(&Bs[r * 36 + lcol]),
                       W + (size_t)(n0 + r) * CHANNELS + k0 + lcol);
        }
        cp_commit();
    };

    auto compute = [&](int st) {
        float* As = smem + st * STAGE_FLOATS;
        float* Bs = As + 4608;
        #pragma unroll
        for (int ks = 0; ks < 4; ks++) {
            const int kk = ks * 8;
            uint32_t a[2][4], bfr[8][2];
            #pragma unroll
            for (int mi = 0; mi < 2; mi++) {
                int r = wm * 32 + mi * 16 + gid;
                a[mi][0] = f2tf32(As[r * 36 + kk + tig]);
                a[mi][1] = f2tf32(As[(r + 8) * 36 + kk + tig]);
                a[mi][2] = f2tf32(As[r * 36 + kk + tig + 4]);
                a[mi][3] = f2tf32(As[(r + 8) * 36 + kk + tig + 4]);
            }
            #pragma unroll
            for (int ni = 0; ni < 8; ni++) {
                int c = wn * 64 + ni * 8 + gid;
                bfr[ni][0] = f2tf32(Bs[c * 36 + kk + tig]);
                bfr[ni][1] = f2tf32(Bs[c * 36 + kk + tig + 4]);
            }
            #pragma unroll
            for (int mi = 0; mi < 2; mi++)
                #pragma unroll
                for (int ni = 0; ni < 8; ni++)
                    mma_tf32(acc[mi][ni], a[mi], bfr[ni]);
        }
    };

    issue(0, 0);
    #pragma unroll 1
    for (int kt = 0; kt < 32; kt++) {
        if (kt + 1 < 32) { issue(kt + 1, (kt + 1) & 1); cp_wait<1>(); }
        else             { cp_wait<0>(); }
        __syncthreads();
        compute(kt & 1);
        __syncthreads();
    }

    #pragma unroll
    for (int mi = 0; mi < 2; mi++) {
        int r = m0 + wm * 32 + mi * 16 + gid;
        #pragma unroll
        for (int ni = 0; ni < 8; ni++) {
            int c = n0 + wn * 64 + ni * 8 + 2 * tig;
            float2 bv = *reinterpret_cast<const float2*>(bias + c);
            float2 o0, o1;
            o0.x = tanhf(acc[mi][ni][0] + bv.x);
            o0.y = tanhf(acc[mi][ni][1] + bv.y);
            o1.x = tanhf(acc[mi][ni][2] + bv.x);
            o1.y = tanhf(acc[mi][ni][3] + bv.y);
            *reinterpret_cast<float2*>(out + (size_t)r * CHANNELS + c)       = o0;
            *reinterpret_cast<float2*>(out + (size_t)(r + 8) * CHANNELS + c) = o1;
        }
    }
}

// ============================================================
// Kernel 2: Jacobian part.
// Virtual A row m = 2p+k:  A[m,j] = J[p*2048 + 2j + k]  (J = x_Jx + PIVOT*1024)
// C[m,i] = sum_j W[i,j] A[m,j];  out2[p*2048 + 2i + k] = (1-h[p,i]^2)*C[m,i]
// block tile: 64 p-rows (=128 virtual rows) x 128 i, k-tile 32.
// ============================================================
__global__ void __launch_bounds__(256) k2_jac(
    const float* __restrict__ J, const float* __restrict__ W,
    const float* __restrict__ h, float* __restrict__ out2)
{
    extern __shared__ float smem[];
    const int tid  = threadIdx.x;
    const int lane = tid & 31, warp = tid >> 5;
    const int gid  = lane >> 2, tig = lane & 3;
    const int wm   = warp >> 1, wn  = warp & 1;
    const int p0   = blockIdx.y * 64, n0 = blockIdx.x * 128;
    const int lrow = tid >> 3, lcol = (tid & 7) * 4;

    float acc[2][8][4];
    #pragma unroll
    for (int i = 0; i < 2; i++)
        #pragma unroll
        for (int j = 0; j < 8; j++)
            #pragma unroll
            for (int k = 0; k < 4; k++) acc[i][j][k] = 0.f;

    auto issue = [&](int kt, int st) {
        float* As = smem + st * STAGE_FLOATS;   // [64][72]: [p][j][k] interleaved
        float* Bs = As + 4608;                  // [128][36]: W rows
        const int k0 = kt * 32;
        #pragma unroll
        for (int it = 0; it < 4; it++) {
            int idx = tid + it * 256;           // 1024 float4 loads for A
            int p = idx >> 4, j2 = idx & 15;    // chunk j2 covers j-cols {2*j2, 2*j2+1}
            cp_async16(smem_addr(&As[p * 72 + 4 * j2]),
                       J + (size_t)(p0 + p) * 2048 + 2 * k0 + 4 * j2);
            cp_async16(smem_addr(&Bs[(lrow + it * 32) * 36 + lcol]),
                       W + (size_t)(n0 + lrow + it * 32) * CHANNELS + k0 + lcol);
        }
        cp_commit();
    };

    auto compute = [&](int st) {
        float* As = smem + st * STAGE_FLOATS;
        float* Bs = As + 4608;
        #pragma unroll
        for (int ks = 0; ks < 4; ks++) {
            const int kk = ks * 8;
            uint32_t a[2][4], bfr[8][2];
            #pragma unroll
            for (int mi = 0; mi < 2; mi++) {
                int m  = wm * 32 + mi * 16 + gid;
                int pl = m >> 1, kb = m & 1;
                a[mi][0] = f2tf32(As[pl * 72 + 2 * (kk + tig) + kb]);
                a[mi][1] = f2tf32(As[(pl + 4) * 72 + 2 * (kk + tig) + kb]);
                a[mi][2] = f2tf32(As[pl * 72 + 2 * (kk + tig + 4) + kb]);
                a[mi][3] = f2tf32(As[(pl + 4) * 72 + 2 * (kk + tig + 4) + kb]);
            }
            #pragma unroll
            for (int ni = 0; ni < 8; ni++) {
                int c = wn * 64 + ni * 8 + gid;
                bfr[ni][0] = f2tf32(Bs[c * 36 + kk + tig]);
                bfr[ni][1] = f2tf32(Bs[c * 36 + kk + tig + 4]);
            }
            #pragma unroll
            for (int mi = 0; mi < 2; mi++)
                #pragma unroll
                for (int ni = 0; ni < 8; ni++)
                    mma_tf32(acc[mi][ni], a[mi], bfr[ni]);
        }
    };

    issue(0, 0);
    #pragma unroll 1
    for (int kt = 0; kt < 32; kt++) {
        if (kt + 1 < 32) { issue(kt + 1, (kt + 1) & 1); cp_wait<1>(); }
        else             { cp_wait<0>(); }
        __syncthreads();
        compute(kt & 1);
        __syncthreads();
    }

    // Stage h tile (64 p-rows x 128 i) into smem: hs[64][132]
    __syncthreads();
    float* hs = smem;
    #pragma unroll
    for (int it = 0; it < 8; it++) {
        int idx = tid + it * 256;           // 2048 float4
        int pl = idx >> 5, i4 = (idx & 31) * 4;
        float4 v = *reinterpret_cast<const float4*>(h + (size_t)(p0 + pl) * CHANNELS + n0 + i4);
        *reinterpret_cast<float4*>(&hs[pl * 132 + i4]) = v;
    }
    __syncthreads();

    #pragma unroll
    for (int mi = 0; mi < 2; mi++) {
        int mv  = wm * 32 + mi * 16 + gid;
        int pl0 = mv >> 1, kb = mv & 1;
        int pl1 = pl0 + 4;
        #pragma unroll
        for (int ni = 0; ni < 8; ni++) {
            int il = wn * 64 + ni * 8 + 2 * tig;
            float h00 = hs[pl0 * 132 + il], h01 = hs[pl0 * 132 + il + 1];
            float h10 = hs[pl1 * 132 + il], h11 = hs[pl1 * 132 + il + 1];
            size_t b0 = (size_t)(p0 + pl0) * 2048 + 2 * (size_t)(n0 + il) + kb;
            size_t b1 = (size_t)(p0 + pl1) * 2048 + 2 * (size_t)(n0 + il) + kb;
            out2[b0]     = (1.f - h00 * h00) * acc[mi][ni][0];
            out2[b0 + 2] = (1.f - h01 * h01) * acc[mi][ni][1];
            out2[b1]     = (1.f - h10 * h10) * acc[mi][ni][2];
            out2[b1 + 2] = (1.f - h11 * h11) * acc[mi][ni][3];
        }
    }
}

// ============================================================
extern "C" void kernel_launch(void* const* d_in, const int* in_sizes, int n_in,
                              void* d_out, int out_size)
{
    const float* x = (const float*)d_in[0];   // [3*PIVOT, CHANNELS]
    const float* W = (const float*)d_in[1];   // [CHANNELS, CHANNELS]
    const float* b = (const float*)d_in[2];   // [CHANNELS]
    float* out = (float*)d_out;               // [3*PIVOT, CHANNELS]

    cudaFuncSetAttribute(k1_gemm_tanh, cudaFuncAttributeMaxDynamicSharedMemorySize, SMEM_BYTES);
    cudaFuncSetAttribute(k2_jac,       cudaFuncAttributeMaxDynamicSharedMemorySize, SMEM_BYTES);

    dim3 g1(CHANNELS / 128, PIVOT / 128);          // (8, 128)
    k1_gemm_tanh<<<g1, 256, SMEM_BYTES>>>(x, W, b, out);

    dim3 g2(CHANNELS / 128, (2 * PIVOT) / 128);    // (8, 256)
    k2_jac<<<g2, 256, SMEM_BYTES>>>(x + (size_t)PIVOT * CHANNELS, W,
                                    out, out + (size_t)PIVOT * CHANNELS);
}

// round 4
// speedup vs baseline: 2.8640x; 2.8640x over previous
#include <cuda_runtime.h>
#include <cuda_fp16.h>
#include <cstdint>
#include <cstddef>

#define CHANNELS 1024
#define PIVOT 16384

// tcgen05 is arch-SPECIFIC (sm_103a). The harness also runs a non-'a'
// compute_103 ptxas pass; emit a plain-CUDA fallback body there.
#if defined(__CUDA_ARCH_FEAT_SM103_ALL) || defined(__CUDA_ARCH_FEAT_SM100_ALL) || defined(__CUDA_ARCH_SPECIFIC__)
#define HAS_TCGEN05 1
#else
#define HAS_TCGEN05 0
#endif

// ---------------- scratch (static device arrays are allowed) ----------
__device__ __half Xh_g[(size_t)PIVOT * CHANNELS];        // 32 MB
__device__ __half Wh_g[(size_t)CHANNELS * CHANNELS];     //  2 MB
__device__ __half A2_g[(size_t)2 * PIVOT * CHANNELS];    // 64 MB (deinterleaved J)

// ---------------- PTX helpers ----------------
__device__ __forceinline__ uint32_t smem_u32(const void* p) {
    uint32_t r;
    asm("{ .reg .u64 t; cvta.to.shared.u64 t, %1; cvt.u32.u64 %0, t; }" : "=r"(r) : "l"(p));
    return r;
}
__device__ __forceinline__ void cp_async16(uint32_t d, const void* s) {
    asm volatile("cp.async.cg.shared.global [%0], [%1], 16;" :: "r"(d), "l"(s));
}
__device__ __forceinline__ void cp_commit() { asm volatile("cp.async.commit_group;"); }
template<int N> __device__ __forceinline__ void cp_wait() {
    asm volatile("cp.async.wait_group %0;" :: "n"(N));
}
__device__ __forceinline__ uint32_t elect_one() {
    uint32_t p;
    asm volatile("{ .reg .pred p; elect.sync _|p, 0xFFFFFFFF; selp.b32 %0, 1, 0, p; }" : "=r"(p));
    return p;
}
#define SW128(x) ((x) ^ (((x) >> 3) & 0x70))

// SW128 K-major smem descriptor (layout=2, version=1, SBO=64, LBO=1)
__device__ __forceinline__ uint64_t make_desc(uint32_t addr) {
    const uint64_t base = (uint64_t(2) << 61) | (uint64_t(1) << 46)
                        | (uint64_t(64) << 32) | (uint64_t(1) << 16);
    return base | ((uint64_t)(addr >> 4) & 0x3FFF);
}

#if HAS_TCGEN05
#define TCG_ALLOC(smem_res, ncols) \
    asm volatile("tcgen05.alloc.cta_group::1.sync.aligned.shared::cta.b32 [%0], %1;" \
                 :: "r"(smem_res), "r"((uint32_t)(ncols)) : "memory")
#define TCG_DEALLOC(tmem, ncols) \
    asm volatile("tcgen05.dealloc.cta_group::1.sync.aligned.b32 %0, %1;" \
                 :: "r"(tmem), "r"((uint32_t)(ncols)))
#define TCG_COMMIT(mbar) \
    asm volatile("tcgen05.commit.cta_group::1.mbarrier::arrive::one.shared::cluster.b64 [%0];" \
                 :: "r"(mbar) : "memory")
#define TCG_FENCE_AFTER()  asm volatile("tcgen05.fence::after_thread_sync;" ::: "memory")
#define TCG_FENCE_BEFORE() asm volatile("tcgen05.fence::before_thread_sync;" ::: "memory")
#define TCG_WAIT_LD()      asm volatile("tcgen05.wait::ld.sync.aligned;" ::: "memory")
#define FENCE_ASYNC()      asm volatile("fence.proxy.async.shared::cta;" ::: "memory")
#define MBAR_INIT(addr, cnt) \
    asm volatile("mbarrier.init.shared.b64 [%0], %1;" :: "r"(addr), "r"((uint32_t)(cnt)) : "memory")
#define MBAR_INVAL(addr) \
    asm volatile("mbarrier.inval.shared.b64 [%0];" :: "r"(addr) : "memory")

__device__ __forceinline__ void mbar_wait(uint32_t addr, uint32_t parity) {
    asm volatile(
        "{\n\t.reg .pred P;\n\t"
        "W_%=:\n\t"
        "mbarrier.try_wait.parity.shared.b64 P, [%0], %1;\n\t"
        "@!P bra W_%=;\n\t}"
        :: "r"(addr), "r"(parity) : "memory");
}

__device__ __forceinline__ void mma_f16_ss(uint32_t d_tmem, uint64_t a_desc,
                                           uint64_t b_desc, uint32_t idesc, uint32_t en) {
    asm volatile(
        "{\n\t.reg .pred p;\n\t"
        "setp.ne.u32 p, %4, 0;\n\t"
        "tcgen05.mma.cta_group::1.kind::f16 [%0], %1, %2, %3, {%5,%5,%5,%5}, p;\n\t}"
        :: "r"(d_tmem), "l"(a_desc), "l"(b_desc), "r"(idesc), "r"(en), "r"(0u) : "memory");
}

#define TCG_LD_X32(r, addr) \
    asm volatile( \
        "tcgen05.ld.sync.aligned.32x32b.x32.b32 " \
        "{%0, %1, %2, %3, %4, %5, %6, %7, " \
        " %8, %9, %10, %11, %12, %13, %14, %15, " \
        " %16, %17, %18, %19, %20, %21, %22, %23, " \
        " %24, %25, %26, %27, %28, %29, %30, %31}, [%32];" \
        : "=r"((r)[0]),  "=r"((r)[1]),  "=r"((r)[2]),  "=r"((r)[3]), \
          "=r"((r)[4]),  "=r"((r)[5]),  "=r"((r)[6]),  "=r"((r)[7]), \
          "=r"((r)[8]),  "=r"((r)[9]),  "=r"((r)[10]), "=r"((r)[11]), \
          "=r"((r)[12]), "=r"((r)[13]), "=r"((r)[14]), "=r"((r)[15]), \
          "=r"((r)[16]), "=r"((r)[17]), "=r"((r)[18]), "=r"((r)[19]), \
          "=r"((r)[20]), "=r"((r)[21]), "=r"((r)[22]), "=r"((r)[23]), \
          "=r"((r)[24]), "=r"((r)[25]), "=r"((r)[26]), "=r"((r)[27]), \
          "=r"((r)[28]), "=r"((r)[29]), "=r"((r)[30]), "=r"((r)[31]) \
        : "r"(addr))
#endif  // HAS_TCGEN05

// ---------------- convert kernels ----------------
__global__ void cvt_XW(const float* __restrict__ X, const float* __restrict__ W) {
    const size_t NX = (size_t)PIVOT * CHANNELS / 4;
    const size_t NW = (size_t)CHANNELS * CHANNELS / 4;
    size_t i = (size_t)blockIdx.x * blockDim.x + threadIdx.x;
    if (i < NX) {
        float4 f = reinterpret_cast<const float4*>(X)[i];
        __half2* o = reinterpret_cast<__half2*>(Xh_g) + i * 2;
        o[0] = __floats2half2_rn(f.x, f.y);
        o[1] = __floats2half2_rn(f.z, f.w);
    } else if (i < NX + NW) {
        size_t j = i - NX;
        float4 f = reinterpret_cast<const float4*>(W)[j];
        __half2* o = reinterpret_cast<__half2*>(Wh_g) + j * 2;
        o[0] = __floats2half2_rn(f.x, f.y);
        o[1] = __floats2half2_rn(f.z, f.w);
    }
}

// Deinterleave J: A2[2p+k][j] = J[p][2j+k]
__global__ void cvt_J(const float* __restrict__ J) {
    size_t i = (size_t)blockIdx.x * blockDim.x + threadIdx.x;  // float4 index
    size_t p = i >> 9, q = i & 511;  // float4 q covers j=2q,2q+1 for both k
    float4 f = reinterpret_cast<const float4*>(J)[i];
    reinterpret_cast<__half2*>(A2_g + (2 * p) * CHANNELS)[q]     = __floats2half2_rn(f.x, f.z);
    reinterpret_cast<__half2*>(A2_g + (2 * p + 1) * CHANNELS)[q] = __floats2half2_rn(f.y, f.w);
}

// ---------------- tcgen05 GEMM ----------------
#define BM 256
#define BN 256
#define BK 64
#define STAGES 3
#define KTILES (CHANNELS / BK)                 // 16
#define STAGE_BYTES (BM * 128 + BN * 128)      // 64 KB
#define SMEM_STAGE0 2048
#define SMEM_TOTAL (SMEM_STAGE0 + STAGES * STAGE_BYTES)   // 198656 B
// idesc: f32 acc (1<<4), f16 a/b (0), N=256 -> (N/8)<<17, M=128 -> (M/16)<<24
#define IDESC ((1u << 4) | ((BN / 8) << 17) | (8u << 24))

// EPI: 0 = tanh(D + bias) -> out rows [m0..m0+255]
//      1 = (1-h^2)*D interleaved -> out2
template<int EPI>
__global__ void __launch_bounds__(256, 1) gemm_tc(
    const float* __restrict__ aux,   // EPI0: bias[1024]; EPI1: h = out[0:PIVOT]
    float* __restrict__ outp)        // EPI0: out base;   EPI1: out2 base
{
#if HAS_TCGEN05
    extern __shared__ char smem[];
    const uint32_t sbase = smem_u32(smem);
    const int tid = threadIdx.x, wid = tid >> 5, lane = tid & 31;
    const int m0 = blockIdx.y * BM, n0 = blockIdx.x * BN;
    const __half* __restrict__ A = (EPI == 0) ? Xh_g : A2_g;

    if (wid == 0) TCG_ALLOC(sbase, 512);
    if (tid == 0) {
        #pragma unroll
        for (int s = 0; s < STAGES; s++) MBAR_INIT(sbase + 8 + 8 * s, 1);
    }
    __syncthreads();
    uint32_t tmem;
    asm volatile("ld.shared.b32 %0, [%1];" : "=r"(tmem) : "r"(sbase));

    auto load_tile = [&](int s, int kt) {
        char* stg = smem + SMEM_STAGE0 + s * STAGE_BYTES;
        char* Bst = stg + BM * 128;
        const int k0 = kt * BK;
        #pragma unroll
        for (int it = 0; it < 8; it++) {
            int chunk = tid + it * 256;       // 0..2047
            int r = chunk >> 3, c = chunk & 7;
            cp_async16(smem_u32(stg + SW128(r * 128 + c * 16)),
                       A + (size_t)(m0 + r) * CHANNELS + k0 + c * 8);
        }
        #pragma unroll
        for (int it = 0; it < 8; it++) {
            int chunk = tid + it * 256;
            int r = chunk >> 3, c = chunk & 7;
            cp_async16(smem_u32(Bst + SW128(r * 128 + c * 16)),
                       Wh_g + (size_t)(n0 + r) * CHANNELS + k0 + c * 8);
        }
        cp_commit();
    };

    load_tile(0, 0);
    load_tile(1, 1);

    #pragma unroll 1
    for (int kt = 0; kt < KTILES; kt++) {
        const int s = kt % STAGES;
        if (kt == KTILES - 1) cp_wait<0>(); else cp_wait<1>();
        __syncthreads();
        FENCE_ASYNC();
        if (wid == 0) {
            if (elect_one()) {
                uint32_t stg = sbase + SMEM_STAGE0 + s * STAGE_BYTES;
                uint64_t ad = make_desc(stg);
                uint64_t bd = make_desc(stg + BM * 128);
                #pragma unroll
                for (int h = 0; h < 2; h++)
                    #pragma unroll
                    for (int ks = 0; ks < 4; ks++)
                        mma_f16_ss(tmem + h * 256, ad + h * 1024 + ks * 2, bd + ks * 2,
                                   IDESC, (kt == 0 && ks == 0) ? 0u : 1u);
                TCG_COMMIT(sbase + 8 + 8 * s);
            }
        }
        if (kt + 2 < KTILES) {
            if (kt >= 1) {
                int t = kt - 1;
                mbar_wait(sbase + 8 + 8 * (t % STAGES), (t / STAGES) & 1);
            }
            load_tile((kt + 2) % STAGES, kt + 2);
        }
    }
    { // final MMA completion
        int t = KTILES - 1;
        mbar_wait(sbase + 8 + 8 * (t % STAGES), (t / STAGES) & 1);
    }
    TCG_FENCE_AFTER();
    __syncthreads();

    const int half = wid >> 2, sub = wid & 3;

    if (EPI == 0) {
        float* bs = reinterpret_cast<float*>(smem + 1024);   // 256 floats
        bs[tid] = aux[n0 + tid];
        __syncthreads();
        const int row = m0 + half * 128 + sub * 32 + lane;
        #pragma unroll 1
        for (int cc = 0; cc < 8; cc++) {
            uint32_t d[32];
            TCG_LD_X32(d, tmem + half * 256 + cc * 32);
            TCG_WAIT_LD();
            float* orow = outp + (size_t)row * CHANNELS + n0 + cc * 32;
            #pragma unroll
            for (int j = 0; j < 32; j += 4) {
                float4 o;
                o.x = tanhf(__uint_as_float(d[j + 0]) + bs[cc * 32 + j + 0]);
                o.y = tanhf(__uint_as_float(d[j + 1]) + bs[cc * 32 + j + 1]);
                o.z = tanhf(__uint_as_float(d[j + 2]) + bs[cc * 32 + j + 2]);
                o.w = tanhf(__uint_as_float(d[j + 3]) + bs[cc * 32 + j + 3]);
                *reinterpret_cast<float4*>(orow + j) = o;
            }
        }
    } else {
        // stage h tile: 128 p-rows x 256 cols, row stride 260 floats
        float* hs = reinterpret_cast<float*>(smem + SMEM_STAGE0);
        const int p0 = m0 >> 1;
        #pragma unroll
        for (int it = 0; it < 32; it++) {
            int idx = tid + it * 256;                 // 8192 float4
            int pr = idx >> 6, c4 = (idx & 63) * 4;
            float4 v = *reinterpret_cast<const float4*>(
                aux + (size_t)(p0 + pr) * CHANNELS + n0 + c4);
            *reinterpret_cast<float4*>(hs + pr * 260 + c4) = v;
        }
        __syncthreads();
        const int v = half * 128 + sub * 32 + lane;   // virtual row in tile
        const int pl = v >> 1, kb = v & 1;
        const float* hrow = hs + pl * 260;
        float* obase = outp + (size_t)(p0 + pl) * 2048 + 2 * (size_t)n0 + kb;
        #pragma unroll 1
        for (int cc = 0; cc < 8; cc++) {
            uint32_t d[32];
            TCG_LD_X32(d, tmem + half * 256 + cc * 32);
            TCG_WAIT_LD();
            #pragma unroll
            for (int j = 0; j < 32; j++) {
                float hv = hrow[cc * 32 + j];
                obase[2 * (cc * 32 + j)] = (1.f - hv * hv) * __uint_as_float(d[j]);
            }
        }
    }

    TCG_FENCE_BEFORE();
    __syncthreads();
    if (tid == 0) {
        #pragma unroll
        for (int s = 0; s < STAGES; s++) MBAR_INVAL(sbase + 8 + 8 * s);
    }
    __syncthreads();
    if (wid == 0) TCG_DEALLOC(tmem, 512);

#else  // ---------- non-sm_103a fallback (never runs on the GB300 SASS path) ----------
    const int tid = threadIdx.x;
    const int m0 = blockIdx.y * BM, n0 = blockIdx.x * BN;
    const __half* __restrict__ A = (EPI == 0) ? Xh_g : A2_g;
    for (int idx = tid; idx < BM * BN; idx += blockDim.x) {
        int mi = idx >> 8, ni = idx & 255;
        int m = m0 + mi, n = n0 + ni;
        float acc = 0.f;
        for (int k = 0; k < CHANNELS; k++)
            acc += __half2float(A[(size_t)m * CHANNELS + k]) *
                   __half2float(Wh_g[(size_t)n * CHANNELS + k]);
        if (EPI == 0) {
            outp[(size_t)m * CHANNELS + n] = tanhf(acc + aux[n]);
        } else {
            int p = m >> 1, kb = m & 1;
            float hv = aux[(size_t)p * CHANNELS + n];
            outp[(size_t)p * 2048 + 2 * (size_t)n + kb] = (1.f - hv * hv) * acc;
        }
    }
#endif
}

// ---------------- launcher ----------------
extern "C" void kernel_launch(void* const* d_in, const int* in_sizes, int n_in,
                              void* d_out, int out_size)
{
    const float* x = (const float*)d_in[0];   // [3*PIVOT, CHANNELS]
    const float* W = (const float*)d_in[1];   // [CHANNELS, CHANNELS]
    const float* b = (const float*)d_in[2];   // [CHANNELS]
    float* out = (float*)d_out;

    cudaFuncSetAttribute(gemm_tc<0>, cudaFuncAttributeMaxDynamicSharedMemorySize, SMEM_TOTAL);
    cudaFuncSetAttribute(gemm_tc<1>, cudaFuncAttributeMaxDynamicSharedMemorySize, SMEM_TOTAL);

    const size_t NX = (size_t)PIVOT * CHANNELS / 4;
    const size_t NW = (size_t)CHANNELS * CHANNELS / 4;
    cvt_XW<<<(unsigned)((NX + NW) / 256), 256>>>(x, W);
    cvt_J<<<(unsigned)((size_t)PIVOT * 512 / 256), 256>>>(x + (size_t)PIVOT * CHANNELS);

    dim3 g1(CHANNELS / BN, PIVOT / BM);          // (4, 64)
    gemm_tc<0><<<g1, 256, SMEM_TOTAL>>>(b, out);

    dim3 g2(CHANNELS / BN, (2 * PIVOT) / BM);    // (4, 128)
    gemm_tc<1><<<g2, 256, SMEM_TOTAL>>>(out, out + (size_t)PIVOT * CHANNELS);
}